// round 16
// baseline (speedup 1.0000x reference)
#include <cuda_runtime.h>
#include <cuda_bf16.h>

// Problem constants
#define NTOK 4096            // H*W
#define NB   8               // batch
#define DH   32              // d = C/8
#define CCH  256             // C
#define M_TOT (NB*NTOK)      // 32768 flattened rows
#define LOG2E 1.4426950408889634f
#define NSPLIT 2
#define KV_PER (NTOK / NSPLIT)
#define SOFF 16.0f           // fixed log2-domain softmax offset (exact after normalize)

// ---------------- scratch (device globals; no allocation allowed) ----------
__device__ float g_sig[4];                        // 1/sigma for wf, wg, wh, wv
__device__ __nv_bfloat16 g_wt[96 * CCH];          // W^T (f|g|h), scaled, bf16
__device__ __nv_bfloat16 g_wvt[CCH * DH];         // wv^T (n-major), scaled, bf16
__device__ __nv_bfloat16 g_f[M_TOT * DH];         // K  = x @ kf + bf   (bf16)
__device__ __nv_bfloat16 g_g[M_TOT * DH];         // Q  = (x @ kg + bg)*log2e (bf16)
__device__ __nv_bfloat16 g_h[M_TOT * DH];         // V  = x @ kh + bh   (bf16)
__device__ __nv_bfloat16 g_po[NSPLIT * M_TOT * DH]; // unnormalized partial O (bf16)
__device__ float g_ml[NSPLIT * M_TOT];            // per-row l per split

// ---------------------------------------------------------------------------
// Helpers
// ---------------------------------------------------------------------------
__device__ __forceinline__ unsigned pk_bf2(float lo, float hi) {
    __nv_bfloat162 h = __floats2bfloat162_rn(lo, hi);
    return *reinterpret_cast<unsigned*>(&h);
}
__device__ __forceinline__ unsigned ex2_bf2(unsigned x) {   // 2^each bf16 half
    unsigned r;
    asm("ex2.approx.ftz.bf16x2 %0, %1;" : "=r"(r) : "r"(x));
    return r;
}
__device__ __forceinline__ float lo_f(unsigned u) { return __uint_as_float(u << 16); }
__device__ __forceinline__ float hi_f(unsigned u) { return __uint_as_float(u & 0xFFFF0000u); }
__device__ __forceinline__ void mma_bf16(float c[4],
                                         unsigned a0, unsigned a1, unsigned a2, unsigned a3,
                                         unsigned b0, unsigned b1) {
    asm volatile(
        "mma.sync.aligned.m16n8k16.row.col.f32.bf16.bf16.f32 "
        "{%0,%1,%2,%3}, {%4,%5,%6,%7}, {%8,%9}, {%0,%1,%2,%3};"
        : "+f"(c[0]), "+f"(c[1]), "+f"(c[2]), "+f"(c[3])
        : "r"(a0), "r"(a1), "r"(a2), "r"(a3), "r"(b0), "r"(b1));
}
__device__ __forceinline__ void ldsm_x4(unsigned r[4], unsigned saddr) {
    asm volatile("ldmatrix.sync.aligned.m8n8.x4.shared.b16 {%0,%1,%2,%3}, [%4];"
        : "=r"(r[0]), "=r"(r[1]), "=r"(r[2]), "=r"(r[3]) : "r"(saddr));
}
__device__ __forceinline__ void ldsm_x4_t(unsigned r[4], unsigned saddr) {
    asm volatile("ldmatrix.sync.aligned.m8n8.x4.trans.shared.b16 {%0,%1,%2,%3}, [%4];"
        : "=r"(r[0]), "=r"(r[1]), "=r"(r[2]), "=r"(r[3]) : "r"(saddr));
}
__device__ __forceinline__ void cp_async16(unsigned s, const void* g) {
    asm volatile("cp.async.cg.shared.global [%0], [%1], 16;" :: "r"(s), "l"(g));
}

// ---------------------------------------------------------------------------
// Kernel 1: spectral-norm sigma (4 blocks) + fused scaled-weight preps.
// ---------------------------------------------------------------------------
__global__ void sigma_kernel(const float* __restrict__ wf, const float* __restrict__ uf,
                             const float* __restrict__ wg, const float* __restrict__ ug,
                             const float* __restrict__ wh, const float* __restrict__ uh,
                             const float* __restrict__ wv, const float* __restrict__ uv) {
    __shared__ float su[256];
    __shared__ float sv[256];
    __shared__ float red[256];
    const int b = blockIdx.x, t = threadIdx.x;
    const float* w; const float* u;
    if (b == 0)      { w = wf; u = uf; }
    else if (b == 1) { w = wg; u = ug; }
    else if (b == 2) { w = wh; u = uh; }
    else             { w = wv; u = uv; }

    if (b < 3) {
        if (t < 32) su[t] = u[t];
        __syncthreads();
        float t1 = 0.f;
        #pragma unroll
        for (int c2 = 0; c2 < 32; ++c2) t1 += w[t * 32 + c2] * su[c2];
        red[t] = t1 * t1;
        __syncthreads();
        for (int s = 128; s > 0; s >>= 1) {
            if (t < s) red[t] += red[t + s];
            __syncthreads();
        }
        float inv1 = rsqrtf(fmaxf(red[0], 1e-12f));
        __syncthreads();
        sv[t] = t1 * inv1;
        __syncthreads();
        {
            float p = 0.f;
            int cc = t & 31, r0 = (t >> 5) * 32;
            #pragma unroll
            for (int j = 0; j < 32; ++j) p += sv[r0 + j] * w[(r0 + j) * 32 + cc];
            red[t] = p;
        }
        __syncthreads();
        if (t < 32) {
            float t2 = 0.f;
            #pragma unroll
            for (int k = 0; k < 8; ++k) t2 += red[k * 32 + t];
            float sq = t2 * t2;
            #pragma unroll
            for (int off = 16; off >= 1; off >>= 1)
                sq += __shfl_xor_sync(0xffffffffu, sq, off);
            if (t == 0) {
                float sig = sq * rsqrtf(fmaxf(sq, 1e-12f));
                float is = 1.f / sig;
                g_sig[b] = is;
                red[0] = is;
            }
        }
        __syncthreads();
        float is = red[0];
        #pragma unroll
        for (int i = 0; i < 32; ++i)
            g_wt[(b * 32 + i) * CCH + t] = __float2bfloat16(w[t * 32 + i] * is);
    } else {
        su[t] = u[t];
        __syncthreads();
        {
            int r = t >> 3, j0 = (t & 7) * 32;
            float p = 0.f;
            #pragma unroll
            for (int j = 0; j < 32; ++j) p += w[r * 256 + j0 + j] * su[j0 + j];
            red[t] = p;
        }
        __syncthreads();
        if (t < 32) {
            float t1 = 0.f;
            #pragma unroll
            for (int k = 0; k < 8; ++k) t1 += red[t * 8 + k];
            float sq = t1 * t1;
            #pragma unroll
            for (int off = 16; off >= 1; off >>= 1)
                sq += __shfl_xor_sync(0xffffffffu, sq, off);
            float inv1 = rsqrtf(fmaxf(sq, 1e-12f));
            sv[t] = t1 * inv1;
        }
        __syncthreads();
        float t2 = 0.f;
        #pragma unroll
        for (int rr = 0; rr < 32; ++rr) t2 += sv[rr] * w[rr * 256 + t];
        red[t] = t2 * t2;
        __syncthreads();
        for (int s = 128; s > 0; s >>= 1) {
            if (t < s) red[t] += red[t + s];
            __syncthreads();
        }
        if (t == 0) {
            float n2 = red[0];
            float sig = n2 * rsqrtf(fmaxf(n2, 1e-12f));
            float is = 1.f / sig;
            g_sig[3] = is;
            red[0] = is;
        }
        __syncthreads();
        float is = red[0];
        #pragma unroll
        for (int k = 0; k < 32; ++k)
            g_wvt[t * 32 + k] = __float2bfloat16(w[k * 256 + t] * is);
    }
}

// ---------------------------------------------------------------------------
// Kernel 2: fused Q/K/V projections on bf16 tensor cores, X pipelined.
// ---------------------------------------------------------------------------
#define PXSTR 72
__global__ __launch_bounds__(256, 2) void proj_kernel(
    const float* __restrict__ x,
    const float* __restrict__ bf, const float* __restrict__ bg,
    const float* __restrict__ bh) {
    __shared__ __align__(16) __nv_bfloat16 Xs[128 * PXSTR];
    __shared__ __align__(16) __nv_bfloat16 Wt[96 * PXSTR];
    const int m0  = blockIdx.x * 128;
    const int tid = threadIdx.x;
    const int lane = tid & 31;
    const int w    = tid >> 5;
    const int g    = lane >> 2;
    const int t4   = lane & 3;

    const int xrow = tid >> 4;
    const int xc4  = (tid & 15) * 4;

    float acc[12][4];
    #pragma unroll
    for (int nt = 0; nt < 12; ++nt)
        #pragma unroll
        for (int j = 0; j < 4; ++j) acc[nt][j] = 0.f;

    float4 xreg[8];
    #pragma unroll
    for (int it = 0; it < 8; ++it)
        xreg[it] = *(const float4*)(x + (size_t)(m0 + xrow + it * 16) * 256 + xc4);

    for (int k0 = 0; k0 < 256; k0 += 64) {
        __syncthreads();
        #pragma unroll
        for (int it = 0; it < 8; ++it) {
            float4 v = xreg[it];
            unsigned p0 = pk_bf2(v.x, v.y);
            unsigned p1 = pk_bf2(v.z, v.w);
            *(uint2*)&Xs[(xrow + it * 16) * PXSTR + xc4] = make_uint2(p0, p1);
        }
        #pragma unroll
        for (int it = 0; it < 3; ++it) {
            int e = tid + it * 256;
            int row = e >> 3, seg = (e & 7) * 8;
            *(uint4*)&Wt[row * PXSTR + seg] = *(const uint4*)&g_wt[row * CCH + k0 + seg];
        }
        if (k0 + 64 < 256) {
            #pragma unroll
            for (int it = 0; it < 8; ++it)
                xreg[it] = *(const float4*)(x + (size_t)(m0 + xrow + it * 16) * 256
                                            + k0 + 64 + xc4);
        }
        __syncthreads();

        #pragma unroll
        for (int kk = 0; kk < 4; ++kk) {
            const __nv_bfloat16* ar = &Xs[(w * 16 + g) * PXSTR + kk * 16 + 2 * t4];
            unsigned a0 = *(const unsigned*)(ar);
            unsigned a1 = *(const unsigned*)(ar + 8 * PXSTR);
            unsigned a2 = *(const unsigned*)(ar + 8);
            unsigned a3 = *(const unsigned*)(ar + 8 * PXSTR + 8);
            #pragma unroll
            for (int nt = 0; nt < 12; ++nt) {
                const __nv_bfloat16* br = &Wt[(nt * 8 + g) * PXSTR + kk * 16 + 2 * t4];
                unsigned b0 = *(const unsigned*)(br);
                unsigned b1 = *(const unsigned*)(br + 8);
                mma_bf16(acc[nt], a0, a1, a2, a3, b0, b1);
            }
        }
    }

    const int m = m0 + w * 16 + g;
    #pragma unroll
    for (int nt = 0; nt < 12; ++nt) {
        int col = nt * 8 + 2 * t4;
        int sect = col >> 5, cc = col & 31;
        const float* bias = (sect == 0) ? bf : (sect == 1) ? bg : bh;
        __nv_bfloat16* outp = (sect == 0) ? g_f : (sect == 1) ? g_g : g_h;
        float b0 = bias[cc], b1 = bias[cc + 1];
        float v0 = acc[nt][0] + b0, v1 = acc[nt][1] + b1;
        float v2 = acc[nt][2] + b0, v3 = acc[nt][3] + b1;
        if (sect == 1) { v0 *= LOG2E; v1 *= LOG2E; v2 *= LOG2E; v3 *= LOG2E; }
        *(unsigned*)(outp + (size_t)m * 32 + cc)       = pk_bf2(v0, v1);
        *(unsigned*)(outp + (size_t)(m + 8) * 32 + cc) = pk_bf2(v2, v3);
    }
}

// ---------------------------------------------------------------------------
// Kernel 3: flash attention, bf16 mma + ldmatrix + cp.async double buffer.
// Fixed-offset softmax via ex2.bf16x2; partial O stored bf16, l fp32.
// BM=64 queries/block (4 warps x 16 rows), BN=64 keys/tile, d=32.
// grid (64, 8, NSPLIT=2).
// ---------------------------------------------------------------------------
#define KSTR 40
#define BUFB (64 * KSTR * 2)     // bytes per K (or V) buffer = 5120

__global__ __launch_bounds__(128, 5) void flash_tc_kernel() {
    __shared__ __align__(16) __nv_bfloat16 Ks[2][64 * KSTR];
    __shared__ __align__(16) __nv_bfloat16 Vs[2][64 * KSTR];

    const int b     = blockIdx.y;
    const int q0    = blockIdx.x * 64;
    const int split = blockIdx.z;
    const int tid  = threadIdx.x;
    const int lane = tid & 31;
    const int w    = tid >> 5;
    const int g    = lane >> 2;
    const int t4   = lane & 3;

    const __nv_bfloat16* Qb = g_g + (size_t)b * NTOK * DH;
    const __nv_bfloat16* Kb = g_f + (size_t)b * NTOK * DH;
    const __nv_bfloat16* Vb = g_h + (size_t)b * NTOK * DH;

    const int qrow = q0 + w * 16 + g;
    unsigned qa[2][4];
    #pragma unroll
    for (int kt = 0; kt < 2; ++kt) {
        const __nv_bfloat16* p0 = Qb + (size_t)qrow * DH + kt * 16 + 2 * t4;
        const __nv_bfloat16* p1 = Qb + (size_t)(qrow + 8) * DH + kt * 16 + 2 * t4;
        qa[kt][0] = *(const unsigned*)(p0);
        qa[kt][1] = *(const unsigned*)(p1);
        qa[kt][2] = *(const unsigned*)(p0 + 8);
        qa[kt][3] = *(const unsigned*)(p1 + 8);
    }

    const unsigned ks_u = (unsigned)__cvta_generic_to_shared(Ks);
    const unsigned vs_u = (unsigned)__cvta_generic_to_shared(Vs);
    const int crow = (tid >> 2) & 31;
    const int cseg = tid & 3;
    const unsigned coff = ((crow * KSTR + cseg * 8) << 1);

    const unsigned kfrag = (((lane & 7) * KSTR + (lane >> 3) * 8) << 1);
    const unsigned vfrag = ((lane * KSTR) << 1);
    const unsigned kfb0 = ks_u + kfrag,        kfb1 = ks_u + BUFB + kfrag;
    const unsigned vfb0 = vs_u + vfrag,        vfb1 = vs_u + BUFB + vfrag;

    float Oacc[4][4];
    #pragma unroll
    for (int i = 0; i < 4; ++i)
        #pragma unroll
        for (int j = 0; j < 4; ++j) Oacc[i][j] = 0.f;
    float l0 = 0.f, l1 = 0.f;

    const int kv_beg = split * KV_PER;
    const int ntiles = KV_PER / 64;         // 32

    const __nv_bfloat16* kp = Kb + (size_t)(kv_beg + crow) * DH + cseg * 8;
    const __nv_bfloat16* vp = Vb + (size_t)(kv_beg + crow) * DH + cseg * 8;

    cp_async16(ks_u + coff, kp);
    cp_async16(ks_u + coff + 32 * KSTR * 2, kp + 32 * DH);
    cp_async16(vs_u + coff, vp);
    cp_async16(vs_u + coff + 32 * KSTR * 2, vp + 32 * DH);
    asm volatile("cp.async.commit_group;");
    kp += 64 * DH; vp += 64 * DH;

    for (int t = 0; t < ntiles; ++t) {
        const int buf = t & 1;
        asm volatile("cp.async.wait_group 0;" ::: "memory");
        __syncthreads();

        if (t + 1 < ntiles) {
            unsigned bo = (buf ^ 1) * BUFB;
            cp_async16(ks_u + bo + coff, kp);
            cp_async16(ks_u + bo + coff + 32 * KSTR * 2, kp + 32 * DH);
            cp_async16(vs_u + bo + coff, vp);
            cp_async16(vs_u + bo + coff + 32 * KSTR * 2, vp + 32 * DH);
            asm volatile("cp.async.commit_group;");
            kp += 64 * DH; vp += 64 * DH;
        }

        const unsigned kfb = buf ? kfb1 : kfb0;
        const unsigned vfb = buf ? vfb1 : vfb0;

        // ---- S = Q @ K^T - SOFF (offset folded into accumulator init) ----
        float c[8][4];
        #pragma unroll
        for (int nt = 0; nt < 8; ++nt) {
            unsigned kf[4];
            ldsm_x4(kf, kfb + nt * (8 * KSTR * 2));
            c[nt][0] = c[nt][1] = c[nt][2] = c[nt][3] = -SOFF;
            mma_bf16(c[nt], qa[0][0], qa[0][1], qa[0][2], qa[0][3], kf[0], kf[1]);
            mma_bf16(c[nt], qa[1][0], qa[1][1], qa[1][2], qa[1][3], kf[2], kf[3]);
        }

        // ---- p = ex2 in bf16x2 (2 exps/op); output IS the A-fragment ----
        unsigned af[4][4];
        #pragma unroll
        for (int kt2 = 0; kt2 < 4; ++kt2) {
            af[kt2][0] = ex2_bf2(pk_bf2(c[2 * kt2][0],     c[2 * kt2][1]));
            af[kt2][1] = ex2_bf2(pk_bf2(c[2 * kt2][2],     c[2 * kt2][3]));
            af[kt2][2] = ex2_bf2(pk_bf2(c[2 * kt2 + 1][0], c[2 * kt2 + 1][1]));
            af[kt2][3] = ex2_bf2(pk_bf2(c[2 * kt2 + 1][2], c[2 * kt2 + 1][3]));
            l0 += (lo_f(af[kt2][0]) + hi_f(af[kt2][0]))
                + (lo_f(af[kt2][2]) + hi_f(af[kt2][2]));
            l1 += (lo_f(af[kt2][1]) + hi_f(af[kt2][1]))
                + (lo_f(af[kt2][3]) + hi_f(af[kt2][3]));
        }

        // ---- O += P @ V ----
        #pragma unroll
        for (int nt2 = 0; nt2 < 4; ++nt2) {
            unsigned v1[4], v2[4];
            ldsm_x4_t(v1, vfb + nt2 * 16);
            ldsm_x4_t(v2, vfb + nt2 * 16 + (32 * KSTR * 2));
            mma_bf16(Oacc[nt2], af[0][0], af[0][1], af[0][2], af[0][3], v1[0], v1[1]);
            mma_bf16(Oacc[nt2], af[1][0], af[1][1], af[1][2], af[1][3], v1[2], v1[3]);
            mma_bf16(Oacc[nt2], af[2][0], af[2][1], af[2][2], af[2][3], v2[0], v2[1]);
            mma_bf16(Oacc[nt2], af[3][0], af[3][1], af[3][2], af[3][3], v2[2], v2[3]);
        }
    }

    l0 += __shfl_xor_sync(0xffffffffu, l0, 1);
    l0 += __shfl_xor_sync(0xffffffffu, l0, 2);
    l1 += __shfl_xor_sync(0xffffffffu, l1, 1);
    l1 += __shfl_xor_sync(0xffffffffu, l1, 2);

    // ---- store unnormalized partial O (bf16) + per-row l (fp32) ----
    __nv_bfloat16* po = g_po + (size_t)split * (M_TOT * DH);
    #pragma unroll
    for (int nt2 = 0; nt2 < 4; ++nt2) {
        int col = nt2 * 8 + 2 * t4;
        size_t off0 = ((size_t)b * NTOK + qrow) * DH + col;
        size_t off1 = ((size_t)b * NTOK + qrow + 8) * DH + col;
        *(unsigned*)(po + off0) = pk_bf2(Oacc[nt2][0], Oacc[nt2][1]);
        *(unsigned*)(po + off1) = pk_bf2(Oacc[nt2][2], Oacc[nt2][3]);
    }
    if (t4 == 0) {
        size_t r = (size_t)b * NTOK + qrow;
        float* ml = g_ml + (size_t)split * M_TOT;
        ml[r]     = l0;
        ml[r + 8] = l1;
    }
}

// ---------------------------------------------------------------------------
// Kernel 4: combine splits + out = gamma*(attn @ (wv/sigma) + bv) + x
// bf16 tensor cores; bf16 partial-O combine; x loads front-batched.
// grid (512, 2): 64 rows x 128-col half; warp w -> rows (w&3)*16,
// col quarter (w>>2)*64 (8 n-tiles).
// ---------------------------------------------------------------------------
#define OSTR 40
__global__ __launch_bounds__(256) void outproj_kernel(
    const float* __restrict__ bv, const float* __restrict__ x,
    const float* __restrict__ gamma, float* __restrict__ out) {
    __shared__ __align__(16) __nv_bfloat16 As[64 * OSTR];
    __shared__ __align__(16) __nv_bfloat16 Ws[128 * OSTR];
    const int mb  = blockIdx.x * 64;
    const int ch  = blockIdx.y * 128;
    const int tid = threadIdx.x;
    const int lane = tid & 31;
    const int w    = tid >> 5;
    const int g    = lane >> 2;
    const int t4   = lane & 3;

    // combine 2 bf16 splits -> normalized bf16 A tile (64x32)
    #pragma unroll
    for (int it = 0; it < 2; ++it) {
        int idx = tid + it * 256;
        int row = idx >> 3;
        int c4  = (idx & 7) << 2;
        size_t r = (size_t)(mb + row);
        float l = g_ml[r] + g_ml[(size_t)M_TOT + r];
        float inv = 1.f / l;
        uint2 pa = *(const uint2*)(g_po + r * DH + c4);
        uint2 pb = *(const uint2*)(g_po + (size_t)M_TOT * DH + r * DH + c4);
        float s0 = lo_f(pa.x) + lo_f(pb.x);
        float s1 = hi_f(pa.x) + hi_f(pb.x);
        float s2 = lo_f(pa.y) + lo_f(pb.y);
        float s3 = hi_f(pa.y) + hi_f(pb.y);
        unsigned u0 = pk_bf2(s0 * inv, s1 * inv);
        unsigned u1 = pk_bf2(s2 * inv, s3 * inv);
        *(uint2*)&As[row * OSTR + c4] = make_uint2(u0, u1);
    }
    #pragma unroll
    for (int it = 0; it < 2; ++it) {
        int e = tid + it * 256;
        int row = e >> 2, seg = (e & 3) * 8;
        *(uint4*)&Ws[row * OSTR + seg] = *(const uint4*)&g_wvt[(ch + row) * 32 + seg];
    }

    // front-batch x loads only (bias is tiny + L2-hot, loaded inline)
    const int mrow0 = (w & 3) * 16;
    const int nloc  = (w >> 2) * 64;
    const float gm = gamma[0];
    float2 xr0[8], xr1[8];
    #pragma unroll
    for (int nt = 0; nt < 8; ++nt) {
        int col = ch + nloc + nt * 8 + 2 * t4;
        xr0[nt] = *(const float2*)(x + (size_t)(mb + mrow0 + g) * 256 + col);
        xr1[nt] = *(const float2*)(x + (size_t)(mb + mrow0 + g + 8) * 256 + col);
    }
    __syncthreads();

    const unsigned as_u = (unsigned)__cvta_generic_to_shared(As);
    const unsigned ws_u = (unsigned)__cvta_generic_to_shared(Ws);

    unsigned aa[2][4];
    {
        unsigned abase = as_u + (((mrow0 + (lane & 15)) * OSTR + (lane >> 4) * 8) << 1);
        ldsm_x4(aa[0], abase);
        ldsm_x4(aa[1], abase + 32);
    }

    const unsigned wfrag = ws_u + (((lane & 7) * OSTR + (lane >> 3) * 8) << 1);

    #pragma unroll
    for (int nt = 0; nt < 8; ++nt) {
        float acc[4] = {0.f, 0.f, 0.f, 0.f};
        unsigned bf4[4];
        ldsm_x4(bf4, wfrag + ((unsigned)((nloc + nt * 8) * OSTR) << 1));
        mma_bf16(acc, aa[0][0], aa[0][1], aa[0][2], aa[0][3], bf4[0], bf4[1]);
        mma_bf16(acc, aa[1][0], aa[1][1], aa[1][2], aa[1][3], bf4[2], bf4[3]);

        int col = ch + nloc + nt * 8 + 2 * t4;
        float2 bias = *(const float2*)(bv + col);
        size_t off0 = (size_t)(mb + mrow0 + g) * 256 + col;
        size_t off1 = (size_t)(mb + mrow0 + g + 8) * 256 + col;
        *(float2*)(out + off0) = make_float2(gm * (acc[0] + bias.x) + xr0[nt].x,
                                             gm * (acc[1] + bias.y) + xr0[nt].y);
        *(float2*)(out + off1) = make_float2(gm * (acc[2] + bias.x) + xr1[nt].x,
                                             gm * (acc[3] + bias.y) + xr1[nt].y);
    }
}

// ---------------------------------------------------------------------------
extern "C" void kernel_launch(void* const* d_in, const int* in_sizes, int n_in,
                              void* d_out, int out_size) {
    const float* x     = (const float*)d_in[0];
    const float* wf    = (const float*)d_in[1];
    const float* bf    = (const float*)d_in[2];
    const float* uf    = (const float*)d_in[3];
    const float* wg    = (const float*)d_in[4];
    const float* bg    = (const float*)d_in[5];
    const float* ug    = (const float*)d_in[6];
    const float* wh    = (const float*)d_in[7];
    const float* bh    = (const float*)d_in[8];
    const float* uh    = (const float*)d_in[9];
    const float* wv    = (const float*)d_in[10];
    const float* bv    = (const float*)d_in[11];
    const float* uv    = (const float*)d_in[12];
    const float* gamma = (const float*)d_in[13];
    float* out = (float*)d_out;

    sigma_kernel<<<4, 256>>>(wf, uf, wg, ug, wh, uh, wv, uv);
    proj_kernel<<<M_TOT / 128, 256>>>(x, bf, bg, bh);
    flash_tc_kernel<<<dim3(NTOK / 64, NB, NSPLIT), 128>>>();
    outproj_kernel<<<dim3(M_TOT / 64, 2), 256>>>(bv, x, gamma, out);
}

// round 17
// speedup vs baseline: 1.0377x; 1.0377x over previous
#include <cuda_runtime.h>
#include <cuda_bf16.h>

// Problem constants
#define NTOK 4096            // H*W
#define NB   8               // batch
#define DH   32              // d = C/8
#define CCH  256             // C
#define M_TOT (NB*NTOK)      // 32768 flattened rows
#define LOG2E 1.4426950408889634f
#define NSPLIT 2
#define KV_PER (NTOK / NSPLIT)
#define SOFF 16.0f           // fixed log2-domain softmax offset (exact after normalize)

// ---------------- scratch (device globals; no allocation allowed) ----------
__device__ float g_sig[4];                        // 1/sigma for wf, wg, wh, wv
__device__ __nv_bfloat16 g_wt[96 * CCH];          // W^T (f|g|h), scaled, bf16
__device__ __nv_bfloat16 g_wvt[CCH * DH];         // wv^T (n-major), scaled, bf16
__device__ __nv_bfloat16 g_f[M_TOT * DH];         // K  = x @ kf + bf   (bf16)
__device__ __nv_bfloat16 g_g[M_TOT * DH];         // Q  = (x @ kg + bg)*log2e (bf16)
__device__ __nv_bfloat16 g_h[M_TOT * DH];         // V  = x @ kh + bh   (bf16)
__device__ __nv_bfloat16 g_po[NSPLIT * M_TOT * DH]; // unnormalized partial O (bf16)
__device__ float g_ml[NSPLIT * M_TOT];            // per-row l per split

// ---------------------------------------------------------------------------
// Helpers
// ---------------------------------------------------------------------------
__device__ __forceinline__ unsigned pk_bf2(float lo, float hi) {
    __nv_bfloat162 h = __floats2bfloat162_rn(lo, hi);
    return *reinterpret_cast<unsigned*>(&h);
}
__device__ __forceinline__ unsigned ex2_bf2(unsigned x) {   // 2^each bf16 half
    unsigned r;
    asm("ex2.approx.ftz.bf16x2 %0, %1;" : "=r"(r) : "r"(x));
    return r;
}
__device__ __forceinline__ float lo_f(unsigned u) { return __uint_as_float(u << 16); }
__device__ __forceinline__ float hi_f(unsigned u) { return __uint_as_float(u & 0xFFFF0000u); }
__device__ __forceinline__ void mma_bf16(float c[4],
                                         unsigned a0, unsigned a1, unsigned a2, unsigned a3,
                                         unsigned b0, unsigned b1) {
    asm volatile(
        "mma.sync.aligned.m16n8k16.row.col.f32.bf16.bf16.f32 "
        "{%0,%1,%2,%3}, {%4,%5,%6,%7}, {%8,%9}, {%0,%1,%2,%3};"
        : "+f"(c[0]), "+f"(c[1]), "+f"(c[2]), "+f"(c[3])
        : "r"(a0), "r"(a1), "r"(a2), "r"(a3), "r"(b0), "r"(b1));
}
__device__ __forceinline__ void ldsm_x4(unsigned r[4], unsigned saddr) {
    asm volatile("ldmatrix.sync.aligned.m8n8.x4.shared.b16 {%0,%1,%2,%3}, [%4];"
        : "=r"(r[0]), "=r"(r[1]), "=r"(r[2]), "=r"(r[3]) : "r"(saddr));
}
__device__ __forceinline__ void ldsm_x4_t(unsigned r[4], unsigned saddr) {
    asm volatile("ldmatrix.sync.aligned.m8n8.x4.trans.shared.b16 {%0,%1,%2,%3}, [%4];"
        : "=r"(r[0]), "=r"(r[1]), "=r"(r[2]), "=r"(r[3]) : "r"(saddr));
}
__device__ __forceinline__ void cp_async16(unsigned s, const void* g) {
    asm volatile("cp.async.cg.shared.global [%0], [%1], 16;" :: "r"(s), "l"(g));
}

// ---------------------------------------------------------------------------
// Kernel 1: spectral-norm sigma (4 blocks) + fused scaled-weight preps.
// ---------------------------------------------------------------------------
__global__ void sigma_kernel(const float* __restrict__ wf, const float* __restrict__ uf,
                             const float* __restrict__ wg, const float* __restrict__ ug,
                             const float* __restrict__ wh, const float* __restrict__ uh,
                             const float* __restrict__ wv, const float* __restrict__ uv) {
    __shared__ float su[256];
    __shared__ float sv[256];
    __shared__ float red[256];
    const int b = blockIdx.x, t = threadIdx.x;
    const float* w; const float* u;
    if (b == 0)      { w = wf; u = uf; }
    else if (b == 1) { w = wg; u = ug; }
    else if (b == 2) { w = wh; u = uh; }
    else             { w = wv; u = uv; }

    if (b < 3) {
        if (t < 32) su[t] = u[t];
        __syncthreads();
        float t1 = 0.f;
        #pragma unroll
        for (int c2 = 0; c2 < 32; ++c2) t1 += w[t * 32 + c2] * su[c2];
        red[t] = t1 * t1;
        __syncthreads();
        for (int s = 128; s > 0; s >>= 1) {
            if (t < s) red[t] += red[t + s];
            __syncthreads();
        }
        float inv1 = rsqrtf(fmaxf(red[0], 1e-12f));
        __syncthreads();
        sv[t] = t1 * inv1;
        __syncthreads();
        {
            float p = 0.f;
            int cc = t & 31, r0 = (t >> 5) * 32;
            #pragma unroll
            for (int j = 0; j < 32; ++j) p += sv[r0 + j] * w[(r0 + j) * 32 + cc];
            red[t] = p;
        }
        __syncthreads();
        if (t < 32) {
            float t2 = 0.f;
            #pragma unroll
            for (int k = 0; k < 8; ++k) t2 += red[k * 32 + t];
            float sq = t2 * t2;
            #pragma unroll
            for (int off = 16; off >= 1; off >>= 1)
                sq += __shfl_xor_sync(0xffffffffu, sq, off);
            if (t == 0) {
                float sig = sq * rsqrtf(fmaxf(sq, 1e-12f));
                float is = 1.f / sig;
                g_sig[b] = is;
                red[0] = is;
            }
        }
        __syncthreads();
        float is = red[0];
        #pragma unroll
        for (int i = 0; i < 32; ++i)
            g_wt[(b * 32 + i) * CCH + t] = __float2bfloat16(w[t * 32 + i] * is);
    } else {
        su[t] = u[t];
        __syncthreads();
        {
            int r = t >> 3, j0 = (t & 7) * 32;
            float p = 0.f;
            #pragma unroll
            for (int j = 0; j < 32; ++j) p += w[r * 256 + j0 + j] * su[j0 + j];
            red[t] = p;
        }
        __syncthreads();
        if (t < 32) {
            float t1 = 0.f;
            #pragma unroll
            for (int k = 0; k < 8; ++k) t1 += red[t * 8 + k];
            float sq = t1 * t1;
            #pragma unroll
            for (int off = 16; off >= 1; off >>= 1)
                sq += __shfl_xor_sync(0xffffffffu, sq, off);
            float inv1 = rsqrtf(fmaxf(sq, 1e-12f));
            sv[t] = t1 * inv1;
        }
        __syncthreads();
        float t2 = 0.f;
        #pragma unroll
        for (int rr = 0; rr < 32; ++rr) t2 += sv[rr] * w[rr * 256 + t];
        red[t] = t2 * t2;
        __syncthreads();
        for (int s = 128; s > 0; s >>= 1) {
            if (t < s) red[t] += red[t + s];
            __syncthreads();
        }
        if (t == 0) {
            float n2 = red[0];
            float sig = n2 * rsqrtf(fmaxf(n2, 1e-12f));
            float is = 1.f / sig;
            g_sig[3] = is;
            red[0] = is;
        }
        __syncthreads();
        float is = red[0];
        #pragma unroll
        for (int k = 0; k < 32; ++k)
            g_wvt[t * 32 + k] = __float2bfloat16(w[k * 256 + t] * is);
    }
}

// ---------------------------------------------------------------------------
// Kernel 2: fused Q/K/V projections on bf16 tensor cores.
// BM=64 rows, 128-thread CTAs (4 warps x 16 rows), grid 512 for balance.
// X pipelined through registers.
// ---------------------------------------------------------------------------
#define PXSTR 72
__global__ __launch_bounds__(128, 4) void proj_kernel(
    const float* __restrict__ x,
    const float* __restrict__ bf, const float* __restrict__ bg,
    const float* __restrict__ bh) {
    __shared__ __align__(16) __nv_bfloat16 Xs[64 * PXSTR];
    __shared__ __align__(16) __nv_bfloat16 Wt[96 * PXSTR];
    const int m0  = blockIdx.x * 64;
    const int tid = threadIdx.x;
    const int lane = tid & 31;
    const int w    = tid >> 5;     // 0..3
    const int g    = lane >> 2;
    const int t4   = lane & 3;

    const int xrow = tid >> 4;            // 0..7 (row stride 8)
    const int xc4  = (tid & 15) * 4;      // col within 64-chunk

    float acc[12][4];
    #pragma unroll
    for (int nt = 0; nt < 12; ++nt)
        #pragma unroll
        for (int j = 0; j < 4; ++j) acc[nt][j] = 0.f;

    float4 xreg[8];
    #pragma unroll
    for (int it = 0; it < 8; ++it)
        xreg[it] = *(const float4*)(x + (size_t)(m0 + xrow + it * 8) * 256 + xc4);

    for (int k0 = 0; k0 < 256; k0 += 64) {
        __syncthreads();
        #pragma unroll
        for (int it = 0; it < 8; ++it) {
            float4 v = xreg[it];
            unsigned p0 = pk_bf2(v.x, v.y);
            unsigned p1 = pk_bf2(v.z, v.w);
            *(uint2*)&Xs[(xrow + it * 8) * PXSTR + xc4] = make_uint2(p0, p1);
        }
        #pragma unroll
        for (int it = 0; it < 6; ++it) {
            int e = tid + it * 128;
            int row = e >> 3, seg = (e & 7) * 8;
            *(uint4*)&Wt[row * PXSTR + seg] = *(const uint4*)&g_wt[row * CCH + k0 + seg];
        }
        if (k0 + 64 < 256) {
            #pragma unroll
            for (int it = 0; it < 8; ++it)
                xreg[it] = *(const float4*)(x + (size_t)(m0 + xrow + it * 8) * 256
                                            + k0 + 64 + xc4);
        }
        __syncthreads();

        #pragma unroll
        for (int kk = 0; kk < 4; ++kk) {
            const __nv_bfloat16* ar = &Xs[(w * 16 + g) * PXSTR + kk * 16 + 2 * t4];
            unsigned a0 = *(const unsigned*)(ar);
            unsigned a1 = *(const unsigned*)(ar + 8 * PXSTR);
            unsigned a2 = *(const unsigned*)(ar + 8);
            unsigned a3 = *(const unsigned*)(ar + 8 * PXSTR + 8);
            #pragma unroll
            for (int nt = 0; nt < 12; ++nt) {
                const __nv_bfloat16* br = &Wt[(nt * 8 + g) * PXSTR + kk * 16 + 2 * t4];
                unsigned b0 = *(const unsigned*)(br);
                unsigned b1 = *(const unsigned*)(br + 8);
                mma_bf16(acc[nt], a0, a1, a2, a3, b0, b1);
            }
        }
    }

    const int m = m0 + w * 16 + g;
    #pragma unroll
    for (int nt = 0; nt < 12; ++nt) {
        int col = nt * 8 + 2 * t4;
        int sect = col >> 5, cc = col & 31;
        const float* bias = (sect == 0) ? bf : (sect == 1) ? bg : bh;
        __nv_bfloat16* outp = (sect == 0) ? g_f : (sect == 1) ? g_g : g_h;
        float b0 = bias[cc], b1 = bias[cc + 1];
        float v0 = acc[nt][0] + b0, v1 = acc[nt][1] + b1;
        float v2 = acc[nt][2] + b0, v3 = acc[nt][3] + b1;
        if (sect == 1) { v0 *= LOG2E; v1 *= LOG2E; v2 *= LOG2E; v3 *= LOG2E; }
        *(unsigned*)(outp + (size_t)m * 32 + cc)       = pk_bf2(v0, v1);
        *(unsigned*)(outp + (size_t)(m + 8) * 32 + cc) = pk_bf2(v2, v3);
    }
}

// ---------------------------------------------------------------------------
// Kernel 3: flash attention, bf16 mma + ldmatrix + cp.async double buffer.
// Fixed-offset softmax via ex2.bf16x2; partial O stored bf16, l fp32.
// BM=64 queries/block (4 warps x 16 rows), BN=64 keys/tile, d=32.
// grid (64, 8, NSPLIT=2). Occupancy target 6 CTAs/SM (reg cap ~85).
// ---------------------------------------------------------------------------
#define KSTR 40
#define BUFB (64 * KSTR * 2)     // bytes per K (or V) buffer = 5120

__global__ __launch_bounds__(128, 6) void flash_tc_kernel() {
    __shared__ __align__(16) __nv_bfloat16 Ks[2][64 * KSTR];
    __shared__ __align__(16) __nv_bfloat16 Vs[2][64 * KSTR];

    const int b     = blockIdx.y;
    const int q0    = blockIdx.x * 64;
    const int split = blockIdx.z;
    const int tid  = threadIdx.x;
    const int lane = tid & 31;
    const int w    = tid >> 5;
    const int g    = lane >> 2;
    const int t4   = lane & 3;

    const __nv_bfloat16* Qb = g_g + (size_t)b * NTOK * DH;
    const __nv_bfloat16* Kb = g_f + (size_t)b * NTOK * DH;
    const __nv_bfloat16* Vb = g_h + (size_t)b * NTOK * DH;

    const int qrow = q0 + w * 16 + g;
    unsigned qa[2][4];
    #pragma unroll
    for (int kt = 0; kt < 2; ++kt) {
        const __nv_bfloat16* p0 = Qb + (size_t)qrow * DH + kt * 16 + 2 * t4;
        const __nv_bfloat16* p1 = Qb + (size_t)(qrow + 8) * DH + kt * 16 + 2 * t4;
        qa[kt][0] = *(const unsigned*)(p0);
        qa[kt][1] = *(const unsigned*)(p1);
        qa[kt][2] = *(const unsigned*)(p0 + 8);
        qa[kt][3] = *(const unsigned*)(p1 + 8);
    }

    const unsigned ks_u = (unsigned)__cvta_generic_to_shared(Ks);
    const unsigned vs_u = (unsigned)__cvta_generic_to_shared(Vs);
    const int crow = (tid >> 2) & 31;
    const int cseg = tid & 3;
    const unsigned coff = ((crow * KSTR + cseg * 8) << 1);

    const unsigned kfrag = (((lane & 7) * KSTR + (lane >> 3) * 8) << 1);
    const unsigned vfrag = ((lane * KSTR) << 1);
    const unsigned kfb0 = ks_u + kfrag,        kfb1 = ks_u + BUFB + kfrag;
    const unsigned vfb0 = vs_u + vfrag,        vfb1 = vs_u + BUFB + vfrag;

    float Oacc[4][4];
    #pragma unroll
    for (int i = 0; i < 4; ++i)
        #pragma unroll
        for (int j = 0; j < 4; ++j) Oacc[i][j] = 0.f;
    float l0 = 0.f, l1 = 0.f;

    const int kv_beg = split * KV_PER;
    const int ntiles = KV_PER / 64;         // 32

    const __nv_bfloat16* kp = Kb + (size_t)(kv_beg + crow) * DH + cseg * 8;
    const __nv_bfloat16* vp = Vb + (size_t)(kv_beg + crow) * DH + cseg * 8;

    cp_async16(ks_u + coff, kp);
    cp_async16(ks_u + coff + 32 * KSTR * 2, kp + 32 * DH);
    cp_async16(vs_u + coff, vp);
    cp_async16(vs_u + coff + 32 * KSTR * 2, vp + 32 * DH);
    asm volatile("cp.async.commit_group;");
    kp += 64 * DH; vp += 64 * DH;

    for (int t = 0; t < ntiles; ++t) {
        const int buf = t & 1;
        asm volatile("cp.async.wait_group 0;" ::: "memory");
        __syncthreads();

        if (t + 1 < ntiles) {
            unsigned bo = (buf ^ 1) * BUFB;
            cp_async16(ks_u + bo + coff, kp);
            cp_async16(ks_u + bo + coff + 32 * KSTR * 2, kp + 32 * DH);
            cp_async16(vs_u + bo + coff, vp);
            cp_async16(vs_u + bo + coff + 32 * KSTR * 2, vp + 32 * DH);
            asm volatile("cp.async.commit_group;");
            kp += 64 * DH; vp += 64 * DH;
        }

        const unsigned kfb = buf ? kfb1 : kfb0;
        const unsigned vfb = buf ? vfb1 : vfb0;

        // ---- S = Q @ K^T - SOFF (offset folded into accumulator init) ----
        float c[8][4];
        #pragma unroll
        for (int nt = 0; nt < 8; ++nt) {
            unsigned kf[4];
            ldsm_x4(kf, kfb + nt * (8 * KSTR * 2));
            c[nt][0] = c[nt][1] = c[nt][2] = c[nt][3] = -SOFF;
            mma_bf16(c[nt], qa[0][0], qa[0][1], qa[0][2], qa[0][3], kf[0], kf[1]);
            mma_bf16(c[nt], qa[1][0], qa[1][1], qa[1][2], qa[1][3], kf[2], kf[3]);
        }

        // ---- p = ex2 in bf16x2 (2 exps/op); output IS the A-fragment ----
        unsigned af[4][4];
        #pragma unroll
        for (int kt2 = 0; kt2 < 4; ++kt2) {
            af[kt2][0] = ex2_bf2(pk_bf2(c[2 * kt2][0],     c[2 * kt2][1]));
            af[kt2][1] = ex2_bf2(pk_bf2(c[2 * kt2][2],     c[2 * kt2][3]));
            af[kt2][2] = ex2_bf2(pk_bf2(c[2 * kt2 + 1][0], c[2 * kt2 + 1][1]));
            af[kt2][3] = ex2_bf2(pk_bf2(c[2 * kt2 + 1][2], c[2 * kt2 + 1][3]));
            l0 += (lo_f(af[kt2][0]) + hi_f(af[kt2][0]))
                + (lo_f(af[kt2][2]) + hi_f(af[kt2][2]));
            l1 += (lo_f(af[kt2][1]) + hi_f(af[kt2][1]))
                + (lo_f(af[kt2][3]) + hi_f(af[kt2][3]));
        }

        // ---- O += P @ V ----
        #pragma unroll
        for (int nt2 = 0; nt2 < 4; ++nt2) {
            unsigned v1[4], v2[4];
            ldsm_x4_t(v1, vfb + nt2 * 16);
            ldsm_x4_t(v2, vfb + nt2 * 16 + (32 * KSTR * 2));
            mma_bf16(Oacc[nt2], af[0][0], af[0][1], af[0][2], af[0][3], v1[0], v1[1]);
            mma_bf16(Oacc[nt2], af[1][0], af[1][1], af[1][2], af[1][3], v1[2], v1[3]);
            mma_bf16(Oacc[nt2], af[2][0], af[2][1], af[2][2], af[2][3], v2[0], v2[1]);
            mma_bf16(Oacc[nt2], af[3][0], af[3][1], af[3][2], af[3][3], v2[2], v2[3]);
        }
    }

    l0 += __shfl_xor_sync(0xffffffffu, l0, 1);
    l0 += __shfl_xor_sync(0xffffffffu, l0, 2);
    l1 += __shfl_xor_sync(0xffffffffu, l1, 1);
    l1 += __shfl_xor_sync(0xffffffffu, l1, 2);

    // ---- store unnormalized partial O (bf16) + per-row l (fp32) ----
    __nv_bfloat16* po = g_po + (size_t)split * (M_TOT * DH);
    #pragma unroll
    for (int nt2 = 0; nt2 < 4; ++nt2) {
        int col = nt2 * 8 + 2 * t4;
        size_t off0 = ((size_t)b * NTOK + qrow) * DH + col;
        size_t off1 = ((size_t)b * NTOK + qrow + 8) * DH + col;
        *(unsigned*)(po + off0) = pk_bf2(Oacc[nt2][0], Oacc[nt2][1]);
        *(unsigned*)(po + off1) = pk_bf2(Oacc[nt2][2], Oacc[nt2][3]);
    }
    if (t4 == 0) {
        size_t r = (size_t)b * NTOK + qrow;
        float* ml = g_ml + (size_t)split * M_TOT;
        ml[r]     = l0;
        ml[r + 8] = l1;
    }
}

// ---------------------------------------------------------------------------
// Kernel 4: combine splits + out = gamma*(attn @ (wv/sigma) + bv) + x
// bf16 tensor cores; bf16 partial-O combine; x loads front-batched.
// grid (512, 2): 64 rows x 128-col half; warp w -> rows (w&3)*16,
// col quarter (w>>2)*64 (8 n-tiles).
// ---------------------------------------------------------------------------
#define OSTR 40
__global__ __launch_bounds__(256) void outproj_kernel(
    const float* __restrict__ bv, const float* __restrict__ x,
    const float* __restrict__ gamma, float* __restrict__ out) {
    __shared__ __align__(16) __nv_bfloat16 As[64 * OSTR];
    __shared__ __align__(16) __nv_bfloat16 Ws[128 * OSTR];
    const int mb  = blockIdx.x * 64;
    const int ch  = blockIdx.y * 128;
    const int tid = threadIdx.x;
    const int lane = tid & 31;
    const int w    = tid >> 5;
    const int g    = lane >> 2;
    const int t4   = lane & 3;

    // combine 2 bf16 splits -> normalized bf16 A tile (64x32)
    #pragma unroll
    for (int it = 0; it < 2; ++it) {
        int idx = tid + it * 256;
        int row = idx >> 3;
        int c4  = (idx & 7) << 2;
        size_t r = (size_t)(mb + row);
        float l = g_ml[r] + g_ml[(size_t)M_TOT + r];
        float inv = 1.f / l;
        uint2 pa = *(const uint2*)(g_po + r * DH + c4);
        uint2 pb = *(const uint2*)(g_po + (size_t)M_TOT * DH + r * DH + c4);
        float s0 = lo_f(pa.x) + lo_f(pb.x);
        float s1 = hi_f(pa.x) + hi_f(pb.x);
        float s2 = lo_f(pa.y) + lo_f(pb.y);
        float s3 = hi_f(pa.y) + hi_f(pb.y);
        unsigned u0 = pk_bf2(s0 * inv, s1 * inv);
        unsigned u1 = pk_bf2(s2 * inv, s3 * inv);
        *(uint2*)&As[row * OSTR + c4] = make_uint2(u0, u1);
    }
    #pragma unroll
    for (int it = 0; it < 2; ++it) {
        int e = tid + it * 256;
        int row = e >> 2, seg = (e & 3) * 8;
        *(uint4*)&Ws[row * OSTR + seg] = *(const uint4*)&g_wvt[(ch + row) * 32 + seg];
    }

    // front-batch x loads only (bias is tiny + L2-hot, loaded inline)
    const int mrow0 = (w & 3) * 16;
    const int nloc  = (w >> 2) * 64;
    const float gm = gamma[0];
    float2 xr0[8], xr1[8];
    #pragma unroll
    for (int nt = 0; nt < 8; ++nt) {
        int col = ch + nloc + nt * 8 + 2 * t4;
        xr0[nt] = *(const float2*)(x + (size_t)(mb + mrow0 + g) * 256 + col);
        xr1[nt] = *(const float2*)(x + (size_t)(mb + mrow0 + g + 8) * 256 + col);
    }
    __syncthreads();

    const unsigned as_u = (unsigned)__cvta_generic_to_shared(As);
    const unsigned ws_u = (unsigned)__cvta_generic_to_shared(Ws);

    unsigned aa[2][4];
    {
        unsigned abase = as_u + (((mrow0 + (lane & 15)) * OSTR + (lane >> 4) * 8) << 1);
        ldsm_x4(aa[0], abase);
        ldsm_x4(aa[1], abase + 32);
    }

    const unsigned wfrag = ws_u + (((lane & 7) * OSTR + (lane >> 3) * 8) << 1);

    #pragma unroll
    for (int nt = 0; nt < 8; ++nt) {
        float acc[4] = {0.f, 0.f, 0.f, 0.f};
        unsigned bf4[4];
        ldsm_x4(bf4, wfrag + ((unsigned)((nloc + nt * 8) * OSTR) << 1));
        mma_bf16(acc, aa[0][0], aa[0][1], aa[0][2], aa[0][3], bf4[0], bf4[1]);
        mma_bf16(acc, aa[1][0], aa[1][1], aa[1][2], aa[1][3], bf4[2], bf4[3]);

        int col = ch + nloc + nt * 8 + 2 * t4;
        float2 bias = *(const float2*)(bv + col);
        size_t off0 = (size_t)(mb + mrow0 + g) * 256 + col;
        size_t off1 = (size_t)(mb + mrow0 + g + 8) * 256 + col;
        *(float2*)(out + off0) = make_float2(gm * (acc[0] + bias.x) + xr0[nt].x,
                                             gm * (acc[1] + bias.y) + xr0[nt].y);
        *(float2*)(out + off1) = make_float2(gm * (acc[2] + bias.x) + xr1[nt].x,
                                             gm * (acc[3] + bias.y) + xr1[nt].y);
    }
}

// ---------------------------------------------------------------------------
extern "C" void kernel_launch(void* const* d_in, const int* in_sizes, int n_in,
                              void* d_out, int out_size) {
    const float* x     = (const float*)d_in[0];
    const float* wf    = (const float*)d_in[1];
    const float* bf    = (const float*)d_in[2];
    const float* uf    = (const float*)d_in[3];
    const float* wg    = (const float*)d_in[4];
    const float* bg    = (const float*)d_in[5];
    const float* ug    = (const float*)d_in[6];
    const float* wh    = (const float*)d_in[7];
    const float* bh    = (const float*)d_in[8];
    const float* uh    = (const float*)d_in[9];
    const float* wv    = (const float*)d_in[10];
    const float* bv    = (const float*)d_in[11];
    const float* uv    = (const float*)d_in[12];
    const float* gamma = (const float*)d_in[13];
    float* out = (float*)d_out;

    sigma_kernel<<<4, 256>>>(wf, uf, wg, ug, wh, uh, wv, uv);
    proj_kernel<<<M_TOT / 64, 128>>>(x, bf, bg, bh);
    flash_tc_kernel<<<dim3(NTOK / 64, NB, NSPLIT), 128>>>();
    outproj_kernel<<<dim3(M_TOT / 64, 2), 256>>>(bv, x, gamma, out);
}